// round 1
// baseline (speedup 1.0000x reference)
#include <cuda_runtime.h>
#include <math.h>

#define Bn 2
#define Nn 256
#define INDIM 256
#define EDIM 16
#define Hh 8
#define Dd 64
#define INNER 512
#define BHn 16
#define TI 16
#define CH 4

// ---------------- scratch (device globals; no allocation allowed) ----------------
__device__ float g_q[BHn*Nn*Dd];      // [bh][i][d]
__device__ float g_kT[BHn*Dd*Nn];     // [bh][d][j]   (transposed for conflict-free smem scoring)
__device__ float g_v[BHn*Nn*Dd];      // [bh][j][d]
__device__ float g_qwe[BHn*Nn*EDIM];  // [bh][i][c] = sum_d q[bh,i,d] * We[c, h*D+d]
__device__ float g_qbe[BHn*Nn];       // [bh][i]    = sum_d q[bh,i,d] * be[h*D+d]
__device__ float g_means[Nn];         // row means of sim for bh==0 (reference quirk)

// ---------------- projection GEMM: (512x256)@(256x512)+bias, 3x (q,k,v) ----------
__global__ void __launch_bounds__(256) proj_kernel(
    const float* __restrict__ nodes,
    const float* __restrict__ Wq, const float* __restrict__ bq,
    const float* __restrict__ Wk, const float* __restrict__ bk,
    const float* __restrict__ Wv, const float* __restrict__ bv)
{
    const int which = blockIdx.z;
    const float* W    = (which==0) ? Wq : ((which==1) ? Wk : Wv);
    const float* bias = (which==0) ? bq : ((which==1) ? bk : bv);
    __shared__ float As[16][64];   // [k][m]
    __shared__ float Bs[16][64];   // [k][n]
    const int row0 = blockIdx.y * 64;
    const int col0 = blockIdx.x * 64;
    const int t = threadIdx.x;
    const int tx = t & 15, ty = t >> 4;
    float acc[4][4];
    #pragma unroll
    for (int u = 0; u < 4; u++)
        #pragma unroll
        for (int w = 0; w < 4; w++) acc[u][w] = 0.f;

    for (int k0 = 0; k0 < INDIM; k0 += 16) {
        #pragma unroll
        for (int r = 0; r < 4; r++) {
            int idx = t + r*256;
            As[idx & 15][idx >> 4] = nodes[(row0 + (idx >> 4))*INDIM + k0 + (idx & 15)];
        }
        #pragma unroll
        for (int r = 0; r < 4; r++) {
            int idx = t + r*256;
            Bs[idx >> 6][idx & 63] = W[(k0 + (idx >> 6))*INNER + col0 + (idx & 63)];
        }
        __syncthreads();
        #pragma unroll
        for (int k = 0; k < 16; k++) {
            float a0 = As[k][ty*4+0], a1 = As[k][ty*4+1];
            float a2 = As[k][ty*4+2], a3 = As[k][ty*4+3];
            float4 b4 = *reinterpret_cast<const float4*>(&Bs[k][tx*4]);
            acc[0][0] += a0*b4.x; acc[0][1] += a0*b4.y; acc[0][2] += a0*b4.z; acc[0][3] += a0*b4.w;
            acc[1][0] += a1*b4.x; acc[1][1] += a1*b4.y; acc[1][2] += a1*b4.z; acc[1][3] += a1*b4.w;
            acc[2][0] += a2*b4.x; acc[2][1] += a2*b4.y; acc[2][2] += a2*b4.z; acc[2][3] += a2*b4.w;
            acc[3][0] += a3*b4.x; acc[3][1] += a3*b4.y; acc[3][2] += a3*b4.z; acc[3][3] += a3*b4.w;
        }
        __syncthreads();
    }
    #pragma unroll
    for (int u = 0; u < 4; u++) {
        #pragma unroll
        for (int w = 0; w < 4; w++) {
            int row = row0 + ty*4 + u;
            int col = col0 + tx*4 + w;
            float val = acc[u][w] + bias[col];
            int b = row >> 8, i = row & 255, h = col >> 6, d = col & 63;
            int bh = b*Hh + h;
            if (which == 0)      g_q [(bh*Nn + i)*Dd + d] = val;
            else if (which == 1) g_kT[(bh*Dd + d)*Nn + i] = val;
            else                 g_v [(bh*Nn + i)*Dd + d] = val;
        }
    }
}

// ---------------- qWe / qbe precompute ----------------
__global__ void __launch_bounds__(256) qe_kernel(const float* __restrict__ We,
                                                 const float* __restrict__ be)
{
    const int bh = blockIdx.x;
    const int h = bh & 7;
    __shared__ float Wes[EDIM*Dd];
    __shared__ float bes[Dd];
    const int t = threadIdx.x;
    for (int idx = t; idx < EDIM*Dd; idx += 256) {
        int c = idx >> 6, d = idx & 63;
        Wes[c*Dd + d] = We[c*INNER + h*Dd + d];
    }
    if (t < Dd) bes[t] = be[h*Dd + t];
    __syncthreads();
    const int i = t;
    float4 qv[16];
    const float4* qr = reinterpret_cast<const float4*>(&g_q[(bh*Nn + i)*Dd]);
    #pragma unroll
    for (int w = 0; w < 16; w++) qv[w] = qr[w];
    const float4* bes4 = reinterpret_cast<const float4*>(bes);
    float qb = 0.f;
    #pragma unroll
    for (int w = 0; w < 16; w++) {
        float4 bw = bes4[w];
        qb += qv[w].x*bw.x + qv[w].y*bw.y + qv[w].z*bw.z + qv[w].w*bw.w;
    }
    g_qbe[bh*Nn + i] = qb;
    const float4* Wes4 = reinterpret_cast<const float4*>(Wes);
    for (int c = 0; c < EDIM; c++) {
        float s = 0.f;
        #pragma unroll
        for (int w = 0; w < 16; w++) {
            float4 ww = Wes4[c*16 + w];
            s += qv[w].x*ww.x + qv[w].y*ww.y + qv[w].z*ww.z + qv[w].w*ww.w;
        }
        g_qwe[(bh*Nn + i)*EDIM + c] = s;
    }
}

// ---------------- row means of sim[bh=0, i, :] ----------------
__global__ void __launch_bounds__(256) means_kernel(const float* __restrict__ edges)
{
    const int i = blockIdx.x;
    const int j = threadIdx.x;
    __shared__ float qsm[Dd];
    __shared__ float qwes[EDIM];
    __shared__ float qbes_s;
    __shared__ float red[8];
    if (j < Dd)  qsm[j]  = g_q[i*Dd + j];              // bh = 0
    if (j < EDIM) qwes[j] = g_qwe[i*EDIM + j];
    if (j == 0)  qbes_s  = g_qbe[i];
    __syncthreads();
    float acc = 0.f;
    #pragma unroll
    for (int d = 0; d < Dd; d++) acc += qsm[d] * g_kT[d*Nn + j];   // bh = 0
    const float4* ep = reinterpret_cast<const float4*>(edges) + (i*Nn + j)*4;  // b = 0
    float et = 0.f;
    #pragma unroll
    for (int w = 0; w < 4; w++) {
        float4 e = ep[w];
        et += e.x*qwes[w*4+0] + e.y*qwes[w*4+1] + e.z*qwes[w*4+2] + e.w*qwes[w*4+3];
    }
    float sim = (acc + et + qbes_s) * 0.125f;
    #pragma unroll
    for (int o = 16; o > 0; o >>= 1) sim += __shfl_down_sync(0xffffffffu, sim, o);
    if ((j & 31) == 0) red[j >> 5] = sim;
    __syncthreads();
    if (j == 0) {
        float s = 0.f;
        #pragma unroll
        for (int w = 0; w < 8; w++) s += red[w];
        g_means[i] = s * (1.0f / Nn);
    }
}

// ---------------- fused attention ----------------
struct AttnSm {
    float  ks[Dd*Nn];        // [d][j]
    float  vs[Nn*Dd];        // [j][d]
    float4 es[CH*Nn*4];      // staged edges, swizzled: [u][j][ (w + (j>>1)) & 3 ]
    float  qst[Dd*TI];       // [d][ii]
    float  qwe[TI*EDIM];     // [ii][c]
    float  Wes[EDIM*Dd];     // [c][d]
    float4 xs[Nn];           // x for the 4 ii of the current chunk
    float4 red_out[4*Dd];    // [g][d] -> 4 ii
    float4 red_ae[CH*16*4];  // [u][g2][c4]
    float  aes[CH*EDIM];     // [u][c]
    float  qbe[TI];
    float  mns[TI];
    float  bes[Dd];
    float  den[CH];
};

__global__ void __launch_bounds__(256, 1) attn_kernel(
    const float* __restrict__ edges, const float* __restrict__ adjacency,
    const float* __restrict__ We, const float* __restrict__ be,
    float* __restrict__ out)
{
    extern __shared__ char smraw[];
    AttnSm& sm = *reinterpret_cast<AttnSm*>(smraw);
    const int t  = threadIdx.x;
    const int bh = blockIdx.y;
    const int b  = bh >> 3, h = bh & 7;
    const int i0 = blockIdx.x * TI;

    // tile loads
    {
        const float4* src = reinterpret_cast<const float4*>(&g_kT[bh*Dd*Nn]);
        float4* dst = reinterpret_cast<float4*>(sm.ks);
        #pragma unroll
        for (int r = 0; r < 16; r++) dst[t + r*256] = src[t + r*256];
        src = reinterpret_cast<const float4*>(&g_v[bh*Nn*Dd]);
        dst = reinterpret_cast<float4*>(sm.vs);
        #pragma unroll
        for (int r = 0; r < 16; r++) dst[t + r*256] = src[t + r*256];
    }
    for (int idx = t; idx < TI*Dd; idx += 256) {
        int ii = idx & (TI-1), d = idx >> 4;
        sm.qst[d*TI + ii] = g_q[(bh*Nn + i0 + ii)*Dd + d];
    }
    for (int idx = t; idx < TI*EDIM; idx += 256) {
        int ii = idx >> 4, c = idx & 15;
        sm.qwe[ii*EDIM + c] = g_qwe[(bh*Nn + i0 + ii)*EDIM + c];
    }
    for (int idx = t; idx < EDIM*Dd; idx += 256) {
        int c = idx >> 6, d = idx & 63;
        sm.Wes[c*Dd + d] = We[c*INNER + h*Dd + d];
    }
    if (t < TI) { sm.qbe[t] = g_qbe[bh*Nn + i0 + t]; sm.mns[t] = g_means[i0 + t]; }
    if (t < Dd) sm.bes[t] = be[h*Dd + t];
    __syncthreads();

    const float4* qst4 = reinterpret_cast<const float4*>(sm.qst);
    const float4* qwe4 = reinterpret_cast<const float4*>(sm.qwe);
    const float*  xsf  = reinterpret_cast<const float*>(sm.xs);

    for (int chnk = 0; chnk < TI/CH; chnk++) {
        const int iib = chnk * CH;
        // ---- phase A: scores + x for 4 rows simultaneously (thread = j)
        {
            const int j = t;
            float4 acc = make_float4(0.f, 0.f, 0.f, 0.f);
            #pragma unroll
            for (int d = 0; d < Dd; d++) {
                float kv = sm.ks[d*Nn + j];
                float4 q4 = qst4[d*4 + chnk];
                acc.x += q4.x*kv; acc.y += q4.y*kv; acc.z += q4.z*kv; acc.w += q4.w*kv;
            }
            float xv[CH];
            #pragma unroll
            for (int u = 0; u < CH; u++) {
                const int ii = iib + u;
                const int i = i0 + ii;
                const float4* ep = reinterpret_cast<const float4*>(edges) + ((b*Nn + i)*Nn + j)*4;
                float et = 0.f;
                #pragma unroll
                for (int w = 0; w < 4; w++) {
                    float4 e = ep[w];
                    float4 qc = qwe4[ii*4 + w];
                    et += e.x*qc.x + e.y*qc.y + e.z*qc.z + e.w*qc.w;
                    sm.es[(u*Nn + j)*4 + ((w + (j >> 1)) & 3)] = e;   // stage for aE pass
                }
                float a = (u==0) ? acc.x : ((u==1) ? acc.y : ((u==2) ? acc.z : acc.w));
                float sim = (a + et + sm.qbe[ii]) * 0.125f;
                float adjv = adjacency[(b*Nn + i)*Nn + j];
                xv[u] = __expf(sim - sm.mns[ii]) * adjv;
            }
            sm.xs[t] = make_float4(xv[0], xv[1], xv[2], xv[3]);
        }
        __syncthreads();
        // ---- denominators (warps 0..3, one ii each)
        {
            const int lane = t & 31, w = t >> 5;
            if (w < CH) {
                float s = 0.f;
                #pragma unroll
                for (int r = 0; r < 8; r++) {
                    float4 xx = sm.xs[lane + r*32];
                    s += (w==0) ? xx.x : ((w==1) ? xx.y : ((w==2) ? xx.z : xx.w));
                }
                #pragma unroll
                for (int o = 16; o > 0; o >>= 1) s += __shfl_down_sync(0xffffffffu, s, o);
                if (lane == 0) sm.den[w] = s;
            }
        }
        // ---- phase B1: x @ v partials
        {
            const int d = t & 63, g = t >> 6;
            float4 ao = make_float4(0.f, 0.f, 0.f, 0.f);
            for (int jj = g; jj < Nn; jj += 4) {
                float4 x4 = sm.xs[jj];
                float vv = sm.vs[jj*Dd + d];
                ao.x += x4.x*vv; ao.y += x4.y*vv; ao.z += x4.z*vv; ao.w += x4.w*vv;
            }
            sm.red_out[g*Dd + d] = ao;
        }
        // ---- phase B2: x . edges partials (aE)
        {
            const int c4 = t & 3, g2 = (t >> 2) & 15, u = t >> 6;
            float4 ae = make_float4(0.f, 0.f, 0.f, 0.f);
            #pragma unroll
            for (int r = 0; r < 16; r++) {
                int jj = g2 + r*16;
                float x = xsf[jj*4 + u];
                float4 e = sm.es[(u*Nn + jj)*4 + ((c4 + (jj >> 1)) & 3)];
                ae.x += x*e.x; ae.y += x*e.y; ae.z += x*e.z; ae.w += x*e.w;
            }
            sm.red_ae[(u*16 + g2)*4 + c4] = ae;
        }
        __syncthreads();
        // ---- reduce aE
        if (t < CH*EDIM) {
            const int u = t >> 4, c = t & 15;
            const int c4 = c >> 2, comp = c & 3;
            float s = 0.f;
            #pragma unroll
            for (int g2 = 0; g2 < 16; g2++) {
                float4 p = sm.red_ae[(u*16 + g2)*4 + c4];
                s += (comp==0) ? p.x : ((comp==1) ? p.y : ((comp==2) ? p.z : p.w));
            }
            sm.aes[u*EDIM + c] = s;
        }
        __syncthreads();
        // ---- finalize 4 output rows
        {
            const int d = t & 63, u = t >> 6;
            float4 r0 = sm.red_out[0*Dd + d], r1 = sm.red_out[1*Dd + d];
            float4 r2 = sm.red_out[2*Dd + d], r3 = sm.red_out[3*Dd + d];
            float4 rs = make_float4(r0.x+r1.x+r2.x+r3.x, r0.y+r1.y+r2.y+r3.y,
                                    r0.z+r1.z+r2.z+r3.z, r0.w+r1.w+r2.w+r3.w);
            float o = (u==0) ? rs.x : ((u==1) ? rs.y : ((u==2) ? rs.z : rs.w));
            float eterm = 0.f;
            #pragma unroll
            for (int c = 0; c < EDIM; c++) eterm += sm.aes[u*EDIM + c] * sm.Wes[c*Dd + d];
            float dn = sm.den[u];
            float scale = (dn != 0.f) ? (1.f / dn) : 0.f;
            float bterm = (dn != 0.f) ? sm.bes[d] : 0.f;
            const int i = i0 + iib + u;
            out[(b*Nn + i)*INNER + h*Dd + d] = (o + eterm) * scale + bterm;
        }
        __syncthreads();
    }
}

// ---------------- launch ----------------
extern "C" void kernel_launch(void* const* d_in, const int* in_sizes, int n_in,
                              void* d_out, int out_size)
{
    const float* nodes = (const float*)d_in[0];
    const float* edges = (const float*)d_in[1];
    const float* adj   = (const float*)d_in[2];
    const float* Wq = (const float*)d_in[3]; const float* bq = (const float*)d_in[4];
    const float* Wk = (const float*)d_in[5]; const float* bk = (const float*)d_in[6];
    const float* Wv = (const float*)d_in[7]; const float* bv = (const float*)d_in[8];
    const float* We = (const float*)d_in[9]; const float* be = (const float*)d_in[10];
    float* out = (float*)d_out;

    cudaFuncSetAttribute(attn_kernel, cudaFuncAttributeMaxDynamicSharedMemorySize,
                         (int)sizeof(AttnSm));

    proj_kernel<<<dim3(8, 8, 3), 256>>>(nodes, Wq, bq, Wk, bk, Wv, bv);
    qe_kernel<<<BHn, 256>>>(We, be);
    means_kernel<<<Nn, 256>>>(edges);
    attn_kernel<<<dim3(Nn/TI, BHn), 256, sizeof(AttnSm)>>>(edges, adj, We, be, out);
}

// round 2
// speedup vs baseline: 1.0727x; 1.0727x over previous
#include <cuda_runtime.h>
#include <math.h>

#define Bn 2
#define Nn 256
#define INDIM 256
#define EDIM 16
#define Hh 8
#define Dd 64
#define INNER 512
#define BHn 16
#define TI 32
#define CH 4
#define ATH 512

// ---------------- scratch (device globals; no allocation allowed) ----------------
__device__ float g_q[BHn*Nn*Dd];      // [bh][i][d]
__device__ float g_kT[BHn*Dd*Nn];     // [bh][d][j]
__device__ float g_v[BHn*Nn*Dd];      // [bh][j][d]
__device__ float g_qwe[BHn*Nn*EDIM];  // [bh][i][c]
__device__ float g_qbe[BHn*Nn];       // [bh][i]
__device__ float g_means[Nn];         // row means of sim for bh==0 (reference quirk)

// ---------------- projection GEMM: (512x256)@(256x512)+bias, 3x (q,k,v) ----------
__global__ void __launch_bounds__(256) proj_kernel(
    const float* __restrict__ nodes,
    const float* __restrict__ Wq, const float* __restrict__ bq,
    const float* __restrict__ Wk, const float* __restrict__ bk,
    const float* __restrict__ Wv, const float* __restrict__ bv)
{
    const int which = blockIdx.z;
    const float* W    = (which==0) ? Wq : ((which==1) ? Wk : Wv);
    const float* bias = (which==0) ? bq : ((which==1) ? bk : bv);
    __shared__ float As[16][64];   // [k][m]
    __shared__ float Bs[16][64];   // [k][n]
    const int row0 = blockIdx.y * 64;
    const int col0 = blockIdx.x * 64;
    const int t = threadIdx.x;
    const int tx = t & 15, ty = t >> 4;
    float acc[4][4];
    #pragma unroll
    for (int u = 0; u < 4; u++)
        #pragma unroll
        for (int w = 0; w < 4; w++) acc[u][w] = 0.f;

    for (int k0 = 0; k0 < INDIM; k0 += 16) {
        #pragma unroll
        for (int r = 0; r < 4; r++) {
            int idx = t + r*256;
            As[idx & 15][idx >> 4] = nodes[(row0 + (idx >> 4))*INDIM + k0 + (idx & 15)];
        }
        #pragma unroll
        for (int r = 0; r < 4; r++) {
            int idx = t + r*256;
            Bs[idx >> 6][idx & 63] = W[(k0 + (idx >> 6))*INNER + col0 + (idx & 63)];
        }
        __syncthreads();
        #pragma unroll
        for (int k = 0; k < 16; k++) {
            float a0 = As[k][ty*4+0], a1 = As[k][ty*4+1];
            float a2 = As[k][ty*4+2], a3 = As[k][ty*4+3];
            float4 b4 = *reinterpret_cast<const float4*>(&Bs[k][tx*4]);
            acc[0][0] += a0*b4.x; acc[0][1] += a0*b4.y; acc[0][2] += a0*b4.z; acc[0][3] += a0*b4.w;
            acc[1][0] += a1*b4.x; acc[1][1] += a1*b4.y; acc[1][2] += a1*b4.z; acc[1][3] += a1*b4.w;
            acc[2][0] += a2*b4.x; acc[2][1] += a2*b4.y; acc[2][2] += a2*b4.z; acc[2][3] += a2*b4.w;
            acc[3][0] += a3*b4.x; acc[3][1] += a3*b4.y; acc[3][2] += a3*b4.z; acc[3][3] += a3*b4.w;
        }
        __syncthreads();
    }
    #pragma unroll
    for (int u = 0; u < 4; u++) {
        #pragma unroll
        for (int w = 0; w < 4; w++) {
            int row = row0 + ty*4 + u;
            int col = col0 + tx*4 + w;
            float val = acc[u][w] + bias[col];
            int b = row >> 8, i = row & 255, h = col >> 6, d = col & 63;
            int bh = b*Hh + h;
            if (which == 0)      g_q [(bh*Nn + i)*Dd + d] = val;
            else if (which == 1) g_kT[(bh*Dd + d)*Nn + i] = val;
            else                 g_v [(bh*Nn + i)*Dd + d] = val;
        }
    }
}

// ---------------- qWe / qbe precompute (64 blocks: (bh, c-group)) ----------------
__global__ void __launch_bounds__(256) qe_kernel(const float* __restrict__ We,
                                                 const float* __restrict__ be)
{
    const int bh = blockIdx.x;
    const int cg = blockIdx.y;       // 0..3, handles c in [cg*4, cg*4+4)
    const int h = bh & 7;
    __shared__ float Wes[4*Dd];
    __shared__ float bes[Dd];
    const int t = threadIdx.x;
    if (t < 4*Dd) {
        int c = t >> 6, d = t & 63;
        Wes[c*Dd + d] = We[(cg*4 + c)*INNER + h*Dd + d];
    }
    if (cg == 0 && t < Dd) bes[t] = be[h*Dd + t];
    __syncthreads();
    const int i = t;
    float4 qv[16];
    const float4* qr = reinterpret_cast<const float4*>(&g_q[(bh*Nn + i)*Dd]);
    #pragma unroll
    for (int w = 0; w < 16; w++) qv[w] = qr[w];
    if (cg == 0) {
        const float4* bes4 = reinterpret_cast<const float4*>(bes);
        float qb = 0.f;
        #pragma unroll
        for (int w = 0; w < 16; w++) {
            float4 bw = bes4[w];
            qb += qv[w].x*bw.x + qv[w].y*bw.y + qv[w].z*bw.z + qv[w].w*bw.w;
        }
        g_qbe[bh*Nn + i] = qb;
    }
    const float4* Wes4 = reinterpret_cast<const float4*>(Wes);
    #pragma unroll
    for (int c = 0; c < 4; c++) {
        float s = 0.f;
        #pragma unroll
        for (int w = 0; w < 16; w++) {
            float4 ww = Wes4[c*16 + w];
            s += qv[w].x*ww.x + qv[w].y*ww.y + qv[w].z*ww.z + qv[w].w*ww.w;
        }
        g_qwe[(bh*Nn + i)*EDIM + cg*4 + c] = s;
    }
}

// ---------------- row means of sim[bh=0, i, :] ----------------
__global__ void __launch_bounds__(256) means_kernel(const float* __restrict__ edges)
{
    const int i = blockIdx.x;
    const int j = threadIdx.x;
    __shared__ float qsm[Dd];
    __shared__ float qwes[EDIM];
    __shared__ float qbes_s;
    __shared__ float red[8];
    if (j < Dd)  qsm[j]  = g_q[i*Dd + j];              // bh = 0
    if (j < EDIM) qwes[j] = g_qwe[i*EDIM + j];
    if (j == 0)  qbes_s  = g_qbe[i];
    __syncthreads();
    float acc = 0.f;
    #pragma unroll
    for (int d = 0; d < Dd; d++) acc += qsm[d] * g_kT[d*Nn + j];   // bh = 0
    const float4* ep = reinterpret_cast<const float4*>(edges) + (i*Nn + j)*4;  // b = 0
    float et = 0.f;
    #pragma unroll
    for (int w = 0; w < 4; w++) {
        float4 e = ep[w];
        et += e.x*qwes[w*4+0] + e.y*qwes[w*4+1] + e.z*qwes[w*4+2] + e.w*qwes[w*4+3];
    }
    float sim = (acc + et + qbes_s) * 0.125f;
    #pragma unroll
    for (int o = 16; o > 0; o >>= 1) sim += __shfl_down_sync(0xffffffffu, sim, o);
    if ((j & 31) == 0) red[j >> 5] = sim;
    __syncthreads();
    if (j == 0) {
        float s = 0.f;
        #pragma unroll
        for (int w = 0; w < 8; w++) s += red[w];
        g_means[i] = s * (1.0f / Nn);
    }
}

// ---------------- fused attention v2: 512 threads, 32 rows/block, 1 wave ----------
struct AttnSm {
    float  ks[Dd*Nn];        // 64KB [d][j]
    float  vs[Nn*Dd];        // 64KB [j][d]
    float4 es[CH*Nn*4];      // 64KB staged edges, swizzled
    float  qst[Dd*TI];       // 8KB  [d][ii]
    float  qwe[TI*EDIM];     // 2KB  [ii][c]
    float  Wes[EDIM*Dd];     // 4KB  [c][d]
    float4 xs[Nn];           // 4KB  x for 4 rows of current chunk
    float4 red_out[8*Dd];    // 8KB  [g][d]
    float4 red_ae[CH*16*4];  // 4KB  [u][g2][c4]
    float  aes[CH*EDIM];
    float  qbe[TI];
    float  mns[TI];
    float  bes[Dd];
    float  den[CH];
};

__global__ void __launch_bounds__(ATH, 1) attn_kernel(
    const float* __restrict__ edges, const float* __restrict__ adjacency,
    const float* __restrict__ We, const float* __restrict__ be,
    float* __restrict__ out)
{
    extern __shared__ char smraw[];
    AttnSm& sm = *reinterpret_cast<AttnSm*>(smraw);
    const int t  = threadIdx.x;
    const int bh = blockIdx.y;
    const int b  = bh >> 3, h = bh & 7;
    const int i0 = blockIdx.x * TI;

    // ---- tile loads
    {
        const float4* src = reinterpret_cast<const float4*>(&g_kT[bh*Dd*Nn]);
        float4* dst = reinterpret_cast<float4*>(sm.ks);
        #pragma unroll
        for (int r = 0; r < 8; r++) dst[t + r*ATH] = src[t + r*ATH];
        src = reinterpret_cast<const float4*>(&g_v[bh*Nn*Dd]);
        dst = reinterpret_cast<float4*>(sm.vs);
        #pragma unroll
        for (int r = 0; r < 8; r++) dst[t + r*ATH] = src[t + r*ATH];
    }
    #pragma unroll
    for (int r = 0; r < 4; r++) {
        int idx = t + r*ATH;              // 2048 = Dd*TI
        int d = idx >> 5, ii = idx & 31;
        sm.qst[d*TI + ii] = g_q[(bh*Nn + i0 + ii)*Dd + d];
    }
    if (t < TI*EDIM) {
        int ii = t >> 4, c = t & 15;
        sm.qwe[ii*EDIM + c] = g_qwe[(bh*Nn + i0 + ii)*EDIM + c];
    }
    {
        int idx = t - TI*EDIM;            // threads 512..? no: reuse low threads
    }
    if (t < EDIM*Dd) {                    // 1024 threads needed -> two rounds
        // covered below
    }
    for (int idx = t; idx < EDIM*Dd; idx += ATH) {
        int c = idx >> 6, d = idx & 63;
        sm.Wes[c*Dd + d] = We[c*INNER + h*Dd + d];
    }
    if (t < TI) { sm.qbe[t] = g_qbe[bh*Nn + i0 + t]; sm.mns[t] = g_means[i0 + t]; }
    if (t < Dd) sm.bes[t] = be[h*Dd + t];
    __syncthreads();

    const float4* qwe4 = reinterpret_cast<const float4*>(sm.qwe);
    const float*  xsf  = reinterpret_cast<const float*>(sm.xs);
    const int j    = t & 255;
    const int half = t >> 8;              // 0/1 -> rows {0,1} / {2,3} of chunk

    for (int chnk = 0; chnk < TI/CH; chnk++) {
        const int iib = chnk * CH;
        // ---- phase A: prefetch edges, score 2 rows/thread, x
        {
            // prefetch edge rows + adjacency for this thread's 2 rows
            float4 ev[2][4];
            float  adjv[2];
            #pragma unroll
            for (int s = 0; s < 2; s++) {
                const int i = i0 + iib + half*2 + s;
                const float4* ep = reinterpret_cast<const float4*>(edges) + ((b*Nn + i)*Nn + j)*4;
                #pragma unroll
                for (int w = 0; w < 4; w++) ev[s][w] = ep[w];
                adjv[s] = adjacency[(b*Nn + i)*Nn + j];
            }
            // q.k for 2 rows
            float2 acc = make_float2(0.f, 0.f);
            #pragma unroll
            for (int d = 0; d < Dd; d++) {
                float kv = sm.ks[d*Nn + j];
                float2 q2 = *reinterpret_cast<const float2*>(&sm.qst[d*TI + iib + half*2]);
                acc.x += q2.x*kv; acc.y += q2.y*kv;
            }
            float xv[2];
            #pragma unroll
            for (int s = 0; s < 2; s++) {
                const int u  = half*2 + s;
                const int ii = iib + u;
                float et = 0.f;
                #pragma unroll
                for (int w = 0; w < 4; w++) {
                    float4 e = ev[s][w];
                    float4 qc = qwe4[ii*4 + w];
                    et += e.x*qc.x + e.y*qc.y + e.z*qc.z + e.w*qc.w;
                    sm.es[(u*Nn + j)*4 + ((w + (j >> 1)) & 3)] = e;
                }
                float a = s ? acc.y : acc.x;
                float sim = (a + et + sm.qbe[ii]) * 0.125f;
                xv[s] = __expf(sim - sm.mns[ii]) * adjv[s];
            }
            float2* xs2 = reinterpret_cast<float2*>(sm.xs);
            xs2[j*2 + half] = make_float2(xv[0], xv[1]);
        }
        __syncthreads();
        // ---- phase B1: x @ v partials (all 512 threads, 8 j-groups)
        {
            const int d = t & 63, g = t >> 6;
            float4 ao = make_float4(0.f, 0.f, 0.f, 0.f);
            #pragma unroll 4
            for (int jj = g; jj < Nn; jj += 8) {
                float4 x4 = sm.xs[jj];
                float vv = sm.vs[jj*Dd + d];
                ao.x += x4.x*vv; ao.y += x4.y*vv; ao.z += x4.z*vv; ao.w += x4.w*vv;
            }
            sm.red_out[g*Dd + d] = ao;
        }
        // ---- phase B2: x . edges partials (threads 0..255)
        if (t < 256) {
            const int c4 = t & 3, g2 = (t >> 2) & 15, u = t >> 6;
            float4 ae = make_float4(0.f, 0.f, 0.f, 0.f);
            #pragma unroll
            for (int r = 0; r < 16; r++) {
                int jj = g2 + r*16;
                float x = xsf[jj*4 + u];
                float4 e = sm.es[(u*Nn + jj)*4 + ((c4 + (jj >> 1)) & 3)];
                ae.x += x*e.x; ae.y += x*e.y; ae.z += x*e.z; ae.w += x*e.w;
            }
            sm.red_ae[(u*16 + g2)*4 + c4] = ae;
        } else if (t < 384) {
            // ---- denominators: warps 8..11, one u each
            const int lane = t & 31, u = (t >> 5) - 8;
            float s = 0.f;
            #pragma unroll
            for (int r = 0; r < 8; r++) {
                float4 xx = sm.xs[lane + r*32];
                s += (u==0) ? xx.x : ((u==1) ? xx.y : ((u==2) ? xx.z : xx.w));
            }
            #pragma unroll
            for (int o = 16; o > 0; o >>= 1) s += __shfl_down_sync(0xffffffffu, s, o);
            if (lane == 0) sm.den[u] = s;
        }
        __syncthreads();
        // ---- reduce aE
        if (t < CH*EDIM) {
            const int u = t >> 4, c = t & 15;
            const int c4 = c >> 2, comp = c & 3;
            float s = 0.f;
            #pragma unroll
            for (int g2 = 0; g2 < 16; g2++) {
                float4 p = sm.red_ae[(u*16 + g2)*4 + c4];
                s += (comp==0) ? p.x : ((comp==1) ? p.y : ((comp==2) ? p.z : p.w));
            }
            sm.aes[u*EDIM + c] = s;
        }
        __syncthreads();
        // ---- finalize 4 output rows (threads 0..255)
        if (t < 256) {
            const int d = t & 63, u = t >> 6;
            float4 rs = make_float4(0.f, 0.f, 0.f, 0.f);
            #pragma unroll
            for (int g = 0; g < 8; g++) {
                float4 r = sm.red_out[g*Dd + d];
                rs.x += r.x; rs.y += r.y; rs.z += r.z; rs.w += r.w;
            }
            float o = (u==0) ? rs.x : ((u==1) ? rs.y : ((u==2) ? rs.z : rs.w));
            float eterm = 0.f;
            #pragma unroll
            for (int c = 0; c < EDIM; c++) eterm += sm.aes[u*EDIM + c] * sm.Wes[c*Dd + d];
            float dn = sm.den[u];
            float scale = (dn != 0.f) ? (1.f / dn) : 0.f;
            float bterm = (dn != 0.f) ? sm.bes[d] : 0.f;
            const int i = i0 + iib + u;
            out[(b*Nn + i)*INNER + h*Dd + d] = (o + eterm) * scale + bterm;
        }
        __syncthreads();
    }
}

// ---------------- launch ----------------
extern "C" void kernel_launch(void* const* d_in, const int* in_sizes, int n_in,
                              void* d_out, int out_size)
{
    const float* nodes = (const float*)d_in[0];
    const float* edges = (const float*)d_in[1];
    const float* adj   = (const float*)d_in[2];
    const float* Wq = (const float*)d_in[3]; const float* bq = (const float*)d_in[4];
    const float* Wk = (const float*)d_in[5]; const float* bk = (const float*)d_in[6];
    const float* Wv = (const float*)d_in[7]; const float* bv = (const float*)d_in[8];
    const float* We = (const float*)d_in[9]; const float* be = (const float*)d_in[10];
    float* out = (float*)d_out;

    cudaFuncSetAttribute(attn_kernel, cudaFuncAttributeMaxDynamicSharedMemorySize,
                         (int)sizeof(AttnSm));

    proj_kernel<<<dim3(8, 8, 3), 256>>>(nodes, Wq, bq, Wk, bk, Wv, bv);
    qe_kernel<<<dim3(BHn, 4), 256>>>(We, be);
    means_kernel<<<Nn, 256>>>(edges);
    attn_kernel<<<dim3(Nn/TI, BHn), ATH, sizeof(AttnSm)>>>(edges, adj, We, be, out);
}

// round 3
// speedup vs baseline: 1.2445x; 1.1602x over previous
#include <cuda_runtime.h>
#include <math.h>

#define Bn 2
#define Nn 256
#define INDIM 256
#define EDIM 16
#define Hh 8
#define Dd 64
#define INNER 512
#define BHn 16
#define TI 32
#define CH 8
#define ATH 512

// ---------------- scratch (device globals; no allocation allowed) ----------------
__device__ float g_q[BHn*Nn*Dd];      // [bh][i][d]
__device__ float g_kT[BHn*Dd*Nn];     // [bh][d][j]
__device__ float g_v[BHn*Nn*Dd];      // [bh][j][d]
__device__ float g_qwe[BHn*Nn*EDIM];  // [bh][i][c]
__device__ float g_qbe[BHn*Nn];       // [bh][i]
__device__ float g_means[Nn];         // row means of sim for bh==0 (reference quirk)

// ---------------- projection GEMM: (512x256)@(256x512)+bias, 3x (q,k,v) ----------
__global__ void __launch_bounds__(256) proj_kernel(
    const float* __restrict__ nodes,
    const float* __restrict__ Wq, const float* __restrict__ bq,
    const float* __restrict__ Wk, const float* __restrict__ bk,
    const float* __restrict__ Wv, const float* __restrict__ bv)
{
    const int which = blockIdx.z;
    const float* W    = (which==0) ? Wq : ((which==1) ? Wk : Wv);
    const float* bias = (which==0) ? bq : ((which==1) ? bk : bv);
    __shared__ float As[32][65];   // [k][m], padded: store lanes hit distinct banks
    __shared__ float Bs[32][64];   // [k][n]
    const int row0 = blockIdx.y * 64;
    const int col0 = blockIdx.x * 64;
    const int t = threadIdx.x;
    const int tx = t & 15, ty = t >> 4;
    float acc[4][4];
    #pragma unroll
    for (int u = 0; u < 4; u++)
        #pragma unroll
        for (int w = 0; w < 4; w++) acc[u][w] = 0.f;

    for (int k0 = 0; k0 < INDIM; k0 += 32) {
        #pragma unroll
        for (int r = 0; r < 8; r++) {
            int idx = t + r*256;
            As[idx & 31][idx >> 5] = nodes[(row0 + (idx >> 5))*INDIM + k0 + (idx & 31)];
        }
        #pragma unroll
        for (int r = 0; r < 8; r++) {
            int idx = t + r*256;
            Bs[idx >> 6][idx & 63] = W[(k0 + (idx >> 6))*INNER + col0 + (idx & 63)];
        }
        __syncthreads();
        #pragma unroll
        for (int k = 0; k < 32; k++) {
            float a0 = As[k][ty*4+0], a1 = As[k][ty*4+1];
            float a2 = As[k][ty*4+2], a3 = As[k][ty*4+3];
            float4 b4 = *reinterpret_cast<const float4*>(&Bs[k][tx*4]);
            acc[0][0] += a0*b4.x; acc[0][1] += a0*b4.y; acc[0][2] += a0*b4.z; acc[0][3] += a0*b4.w;
            acc[1][0] += a1*b4.x; acc[1][1] += a1*b4.y; acc[1][2] += a1*b4.z; acc[1][3] += a1*b4.w;
            acc[2][0] += a2*b4.x; acc[2][1] += a2*b4.y; acc[2][2] += a2*b4.z; acc[2][3] += a2*b4.w;
            acc[3][0] += a3*b4.x; acc[3][1] += a3*b4.y; acc[3][2] += a3*b4.z; acc[3][3] += a3*b4.w;
        }
        __syncthreads();
    }
    #pragma unroll
    for (int u = 0; u < 4; u++) {
        #pragma unroll
        for (int w = 0; w < 4; w++) {
            int row = row0 + ty*4 + u;
            int col = col0 + tx*4 + w;
            float val = acc[u][w] + bias[col];
            int b = row >> 8, i = row & 255, h = col >> 6, d = col & 63;
            int bh = b*Hh + h;
            if (which == 0)      g_q [(bh*Nn + i)*Dd + d] = val;
            else if (which == 1) g_kT[(bh*Dd + d)*Nn + i] = val;
            else                 g_v [(bh*Nn + i)*Dd + d] = val;
        }
    }
}

// ---------------- qWe / qbe precompute (64 blocks: (bh, c-group)) ----------------
__global__ void __launch_bounds__(256) qe_kernel(const float* __restrict__ We,
                                                 const float* __restrict__ be)
{
    const int bh = blockIdx.x;
    const int cg = blockIdx.y;       // 0..3, handles c in [cg*4, cg*4+4)
    const int h = bh & 7;
    __shared__ float Wes[4*Dd];
    __shared__ float bes[Dd];
    const int t = threadIdx.x;
    if (t < 4*Dd) {
        int c = t >> 6, d = t & 63;
        Wes[c*Dd + d] = We[(cg*4 + c)*INNER + h*Dd + d];
    }
    if (cg == 0 && t < Dd) bes[t] = be[h*Dd + t];
    __syncthreads();
    const int i = t;
    float4 qv[16];
    const float4* qr = reinterpret_cast<const float4*>(&g_q[(bh*Nn + i)*Dd]);
    #pragma unroll
    for (int w = 0; w < 16; w++) qv[w] = qr[w];
    if (cg == 0) {
        const float4* bes4 = reinterpret_cast<const float4*>(bes);
        float qb = 0.f;
        #pragma unroll
        for (int w = 0; w < 16; w++) {
            float4 bw = bes4[w];
            qb += qv[w].x*bw.x + qv[w].y*bw.y + qv[w].z*bw.z + qv[w].w*bw.w;
        }
        g_qbe[bh*Nn + i] = qb;
    }
    const float4* Wes4 = reinterpret_cast<const float4*>(Wes);
    #pragma unroll
    for (int c = 0; c < 4; c++) {
        float s = 0.f;
        #pragma unroll
        for (int w = 0; w < 16; w++) {
            float4 ww = Wes4[c*16 + w];
            s += qv[w].x*ww.x + qv[w].y*ww.y + qv[w].z*ww.z + qv[w].w*ww.w;
        }
        g_qwe[(bh*Nn + i)*EDIM + cg*4 + c] = s;
    }
}

// ---------------- row means of sim[bh=0, i, :] ----------------
__global__ void __launch_bounds__(256) means_kernel(const float* __restrict__ edges)
{
    const int i = blockIdx.x;
    const int j = threadIdx.x;
    __shared__ float qsm[Dd];
    __shared__ float qwes[EDIM];
    __shared__ float qbes_s;
    __shared__ float red[8];
    if (j < Dd)  qsm[j]  = g_q[i*Dd + j];              // bh = 0
    if (j < EDIM) qwes[j] = g_qwe[i*EDIM + j];
    if (j == 0)  qbes_s  = g_qbe[i];
    __syncthreads();
    float acc = 0.f;
    #pragma unroll
    for (int d = 0; d < Dd; d++) acc += qsm[d] * g_kT[d*Nn + j];   // bh = 0
    const float4* ep = reinterpret_cast<const float4*>(edges) + (i*Nn + j)*4;  // b = 0
    float et = 0.f;
    #pragma unroll
    for (int w = 0; w < 4; w++) {
        float4 e = ep[w];
        et += e.x*qwes[w*4+0] + e.y*qwes[w*4+1] + e.z*qwes[w*4+2] + e.w*qwes[w*4+3];
    }
    float sim = (acc + et + qbes_s) * 0.125f;
    #pragma unroll
    for (int o = 16; o > 0; o >>= 1) sim += __shfl_down_sync(0xffffffffu, sim, o);
    if ((j & 31) == 0) red[j >> 5] = sim;
    __syncthreads();
    if (j == 0) {
        float s = 0.f;
        #pragma unroll
        for (int w = 0; w < 8; w++) s += red[w];
        g_means[i] = s * (1.0f / Nn);
    }
}

// ---------------- fused attention v3: CH=8, no edge smem staging ----------------
struct AttnSm {
    float4 xs4[Nn*2];        // 8KB  x for 8 rows: [j][p], p=0 rows0-3, p=1 rows4-7
    float4 red_out[8*Dd*2];  // 16KB [g][d][p]
    float4 red_ae[CH*16];    // 2KB  [u][g2] (c4 folded: see below) -- actually [u*16+g2] per c4
    float4 red_ae2[CH*16*3]; // pad to [u][g2][c4] total 8KB with red_ae
    float  ks[Dd*Nn];        // 64KB [d][j]
    float  vs[Nn*Dd];        // 64KB [j][d]
    float  qst[Dd*TI];       // 8KB  [d][ii]
    float  qwe[TI*EDIM];     // 2KB  [ii][c]
    float  Wes[EDIM*Dd];     // 4KB  [c][d]
    float  aes[CH*EDIM];     // [u][c]
    float  qbe[TI];
    float  mns[TI];
    float  bes[Dd];
    float  den[CH];
};

__global__ void __launch_bounds__(ATH, 1) attn_kernel(
    const float* __restrict__ edges, const float* __restrict__ adjacency,
    const float* __restrict__ We, const float* __restrict__ be,
    float* __restrict__ out)
{
    extern __shared__ char smraw[];
    AttnSm& sm = *reinterpret_cast<AttnSm*>(smraw);
    float4* red_ae = sm.red_ae;  // treat red_ae..red_ae2 as one [u][g2][c4] array (8*16*4)
    const int t  = threadIdx.x;
    const int bh = blockIdx.y;
    const int b  = bh >> 3, h = bh & 7;
    const int i0 = blockIdx.x * TI;

    // ---- tile loads
    {
        const float4* src = reinterpret_cast<const float4*>(&g_kT[bh*Dd*Nn]);
        float4* dst = reinterpret_cast<float4*>(sm.ks);
        #pragma unroll
        for (int r = 0; r < 8; r++) dst[t + r*ATH] = src[t + r*ATH];
        src = reinterpret_cast<const float4*>(&g_v[bh*Nn*Dd]);
        dst = reinterpret_cast<float4*>(sm.vs);
        #pragma unroll
        for (int r = 0; r < 8; r++) dst[t + r*ATH] = src[t + r*ATH];
    }
    #pragma unroll
    for (int r = 0; r < 4; r++) {
        int idx = t + r*ATH;              // 2048 = Dd*TI
        int d = idx >> 5, ii = idx & 31;
        sm.qst[d*TI + ii] = g_q[(bh*Nn + i0 + ii)*Dd + d];
    }
    if (t < TI*EDIM) {
        int ii = t >> 4, c = t & 15;
        sm.qwe[ii*EDIM + c] = g_qwe[(bh*Nn + i0 + ii)*EDIM + c];
    }
    for (int idx = t; idx < EDIM*Dd; idx += ATH) {
        int c = idx >> 6, d = idx & 63;
        sm.Wes[c*Dd + d] = We[c*INNER + h*Dd + d];
    }
    if (t < TI) { sm.qbe[t] = g_qbe[bh*Nn + i0 + t]; sm.mns[t] = g_means[i0 + t]; }
    if (t < Dd) sm.bes[t] = be[h*Dd + t];
    __syncthreads();

    const float4* qst4 = reinterpret_cast<const float4*>(sm.qst);  // [d][8] row-quads
    const float4* qwe4 = reinterpret_cast<const float4*>(sm.qwe);
    const float*  xsf  = reinterpret_cast<const float*>(sm.xs4);   // [j][8]

    for (int chnk = 0; chnk < TI/CH; chnk++) {
        const int iib = chnk * CH;
        // ================= phase A: score 4 rows/thread =================
        {
            const int j = t & 255, half = t >> 8;
            // q.k for 4 rows (float4 accumulator)
            float4 acc = make_float4(0.f, 0.f, 0.f, 0.f);
            #pragma unroll
            for (int d = 0; d < Dd; d++) {
                float kv = sm.ks[d*Nn + j];
                float4 q4 = qst4[d*8 + chnk*2 + half];   // broadcast
                acc.x += q4.x*kv; acc.y += q4.y*kv; acc.z += q4.z*kv; acc.w += q4.w*kv;
            }
            float xv[4];
            #pragma unroll
            for (int s = 0; s < 4; s++) {
                const int u  = half*4 + s;
                const int ii = iib + u;
                const int i  = i0 + ii;
                const float4* ep = reinterpret_cast<const float4*>(edges) + ((b*Nn + i)*Nn + j)*4;
                float4 e0 = ep[0], e1 = ep[1], e2 = ep[2], e3 = ep[3];
                float adjv = adjacency[(b*Nn + i)*Nn + j];
                float4 q0 = qwe4[ii*4+0], q1 = qwe4[ii*4+1];
                float4 q2 = qwe4[ii*4+2], q3 = qwe4[ii*4+3];
                float et = e0.x*q0.x + e0.y*q0.y + e0.z*q0.z + e0.w*q0.w
                         + e1.x*q1.x + e1.y*q1.y + e1.z*q1.z + e1.w*q1.w
                         + e2.x*q2.x + e2.y*q2.y + e2.z*q2.z + e2.w*q2.w
                         + e3.x*q3.x + e3.y*q3.y + e3.z*q3.z + e3.w*q3.w;
                float a = (s==0) ? acc.x : ((s==1) ? acc.y : ((s==2) ? acc.z : acc.w));
                float sim = (a + et + sm.qbe[ii]) * 0.125f;
                xv[s] = __expf(sim - sm.mns[ii]) * adjv;
            }
            sm.xs4[j*2 + half] = make_float4(xv[0], xv[1], xv[2], xv[3]);
        }
        __syncthreads();
        // ================= phase B1: x @ v partials (all 512) =================
        {
            const int d = t & 63, g = t >> 6;
            float4 a0 = make_float4(0.f, 0.f, 0.f, 0.f);
            float4 a1 = make_float4(0.f, 0.f, 0.f, 0.f);
            #pragma unroll 4
            for (int jj = g; jj < Nn; jj += 8) {
                float vv = sm.vs[jj*Dd + d];
                float4 xA = sm.xs4[jj*2 + 0];
                float4 xB = sm.xs4[jj*2 + 1];
                a0.x += xA.x*vv; a0.y += xA.y*vv; a0.z += xA.z*vv; a0.w += xA.w*vv;
                a1.x += xB.x*vv; a1.y += xB.y*vv; a1.z += xB.z*vv; a1.w += xB.w*vv;
            }
            sm.red_out[(g*Dd + d)*2 + 0] = a0;
            sm.red_out[(g*Dd + d)*2 + 1] = a1;
        }
        // ================= phase B2: x . edges (GMEM re-read, L2-hot) ========
        {
            const int c4 = t & 3, g2 = (t >> 2) & 15, u = t >> 6;
            const int i = i0 + iib + u;
            const float4* ebase = reinterpret_cast<const float4*>(edges) + (b*Nn + i)*Nn*4;
            float4 ae = make_float4(0.f, 0.f, 0.f, 0.f);
            #pragma unroll
            for (int r = 0; r < 16; r++) {
                int jj = g2 + r*16;
                float x = xsf[jj*8 + u];
                float4 e = ebase[jj*4 + c4];
                ae.x += x*e.x; ae.y += x*e.y; ae.z += x*e.z; ae.w += x*e.w;
            }
            red_ae[(u*16 + g2)*4 + c4] = ae;
        }
        __syncthreads();
        // ---- reduce aE (threads 0..127) + denominators (warps 4..11)
        if (t < CH*EDIM) {
            const int u = t >> 4, c = t & 15;
            const int c4 = c >> 2, comp = c & 3;
            float s = 0.f;
            #pragma unroll
            for (int g2 = 0; g2 < 16; g2++) {
                float4 p = red_ae[(u*16 + g2)*4 + c4];
                s += (comp==0) ? p.x : ((comp==1) ? p.y : ((comp==2) ? p.z : p.w));
            }
            sm.aes[u*EDIM + c] = s;
        } else if (t < 384) {
            const int lane = t & 31, u = (t >> 5) - 4;   // u = 0..7
            float s = 0.f;
            #pragma unroll
            for (int r = 0; r < 8; r++) {
                int jj = lane + r*32;
                s += xsf[jj*8 + u];
            }
            #pragma unroll
            for (int o = 16; o > 0; o >>= 1) s += __shfl_down_sync(0xffffffffu, s, o);
            if (lane == 0) sm.den[u] = s;
        }
        __syncthreads();
        // ================= finalize 8 output rows (all 512) =================
        {
            const int d = t & 63, u = t >> 6;
            const int p = u >> 2, comp = u & 3;
            float rs = 0.f;
            #pragma unroll
            for (int g = 0; g < 8; g++) {
                float4 r = sm.red_out[(g*Dd + d)*2 + p];
                rs += (comp==0) ? r.x : ((comp==1) ? r.y : ((comp==2) ? r.z : r.w));
            }
            float eterm = 0.f;
            #pragma unroll
            for (int c = 0; c < EDIM; c++) eterm += sm.aes[u*EDIM + c] * sm.Wes[c*Dd + d];
            float dn = sm.den[u];
            float scale = (dn != 0.f) ? (1.f / dn) : 0.f;
            float bterm = (dn != 0.f) ? sm.bes[d] : 0.f;
            const int i = i0 + iib + u;
            out[(b*Nn + i)*INNER + h*Dd + d] = (rs + eterm) * scale + bterm;
        }
        __syncthreads();
    }
}

// ---------------- launch ----------------
extern "C" void kernel_launch(void* const* d_in, const int* in_sizes, int n_in,
                              void* d_out, int out_size)
{
    const float* nodes = (const float*)d_in[0];
    const float* edges = (const float*)d_in[1];
    const float* adj   = (const float*)d_in[2];
    const float* Wq = (const float*)d_in[3]; const float* bq = (const float*)d_in[4];
    const float* Wk = (const float*)d_in[5]; const float* bk = (const float*)d_in[6];
    const float* Wv = (const float*)d_in[7]; const float* bv = (const float*)d_in[8];
    const float* We = (const float*)d_in[9]; const float* be = (const float*)d_in[10];
    float* out = (float*)d_out;

    cudaFuncSetAttribute(attn_kernel, cudaFuncAttributeMaxDynamicSharedMemorySize,
                         (int)sizeof(AttnSm));

    proj_kernel<<<dim3(8, 8, 3), 256>>>(nodes, Wq, bq, Wk, bk, Wv, bv);
    qe_kernel<<<dim3(BHn, 4), 256>>>(We, be);
    means_kernel<<<Nn, 256>>>(edges);
    attn_kernel<<<dim3(Nn/TI, BHn), ATH, sizeof(AttnSm)>>>(edges, adj, We, be, out);
}

// round 4
// speedup vs baseline: 1.3616x; 1.0941x over previous
#include <cuda_runtime.h>
#include <math.h>

#define Bn 2
#define Nn 256
#define INDIM 256
#define EDIM 16
#define Hh 8
#define Dd 64
#define INNER 512
#define BHn 16
#define TI 32
#define CH 16
#define ATH 512
#define XSTR 20   // float stride per j-row of xs (bank-conflict-free padding)

// ---------------- scratch (device globals; no allocation allowed) ----------------
__device__ float g_q[BHn*Nn*Dd];      // [bh][i][d]
__device__ float g_kT[BHn*Dd*Nn];     // [bh][d][j]
__device__ float g_v[BHn*Nn*Dd];      // [bh][j][d]
__device__ float g_means[Nn];         // row means of sim for bh==0 (reference quirk)

// ---------------- projection GEMM: (512x256)@(256x512)+bias, 3x (q,k,v) ----------
__global__ void __launch_bounds__(256) proj_kernel(
    const float* __restrict__ nodes,
    const float* __restrict__ Wq, const float* __restrict__ bq,
    const float* __restrict__ Wk, const float* __restrict__ bk,
    const float* __restrict__ Wv, const float* __restrict__ bv)
{
    const int which = blockIdx.z;
    const float* W    = (which==0) ? Wq : ((which==1) ? Wk : Wv);
    const float* bias = (which==0) ? bq : ((which==1) ? bk : bv);
    __shared__ float As[32][68];   // [k][m]; stride 68: float4-aligned, mild store conflicts
    __shared__ float Bs[32][64];   // [k][n]
    const int row0 = blockIdx.y * 64;
    const int col0 = blockIdx.x * 64;
    const int t = threadIdx.x;
    const int tx = t & 15, ty = t >> 4;
    float acc[4][4];
    #pragma unroll
    for (int u = 0; u < 4; u++)
        #pragma unroll
        for (int w = 0; w < 4; w++) acc[u][w] = 0.f;

    for (int k0 = 0; k0 < INDIM; k0 += 32) {
        #pragma unroll
        for (int r = 0; r < 2; r++) {
            int idx = t + r*256;                 // 512 float4 of A
            int row = idx >> 3, kq = idx & 7;
            float4 nv = *reinterpret_cast<const float4*>(&nodes[(row0+row)*INDIM + k0 + kq*4]);
            As[kq*4+0][row] = nv.x; As[kq*4+1][row] = nv.y;
            As[kq*4+2][row] = nv.z; As[kq*4+3][row] = nv.w;
        }
        #pragma unroll
        for (int r = 0; r < 2; r++) {
            int idx = t + r*256;                 // 512 float4 of B
            int kk = idx >> 4, c4 = idx & 15;
            *reinterpret_cast<float4*>(&Bs[kk][c4*4]) =
                *reinterpret_cast<const float4*>(&W[(k0+kk)*INNER + col0 + c4*4]);
        }
        __syncthreads();
        #pragma unroll
        for (int k = 0; k < 32; k++) {
            float4 a4 = *reinterpret_cast<const float4*>(&As[k][ty*4]);
            float4 b4 = *reinterpret_cast<const float4*>(&Bs[k][tx*4]);
            acc[0][0] += a4.x*b4.x; acc[0][1] += a4.x*b4.y; acc[0][2] += a4.x*b4.z; acc[0][3] += a4.x*b4.w;
            acc[1][0] += a4.y*b4.x; acc[1][1] += a4.y*b4.y; acc[1][2] += a4.y*b4.z; acc[1][3] += a4.y*b4.w;
            acc[2][0] += a4.z*b4.x; acc[2][1] += a4.z*b4.y; acc[2][2] += a4.z*b4.z; acc[2][3] += a4.z*b4.w;
            acc[3][0] += a4.w*b4.x; acc[3][1] += a4.w*b4.y; acc[3][2] += a4.w*b4.z; acc[3][3] += a4.w*b4.w;
        }
        __syncthreads();
    }
    #pragma unroll
    for (int u = 0; u < 4; u++) {
        #pragma unroll
        for (int w = 0; w < 4; w++) {
            int row = row0 + ty*4 + u;
            int col = col0 + tx*4 + w;
            float val = acc[u][w] + bias[col];
            int b = row >> 8, i = row & 255, h = col >> 6, d = col & 63;
            int bh = b*Hh + h;
            if (which == 0)      g_q [(bh*Nn + i)*Dd + d] = val;
            else if (which == 1) g_kT[(bh*Dd + d)*Nn + i] = val;
            else                 g_v [(bh*Nn + i)*Dd + d] = val;
        }
    }
}

// ---------------- row means of sim[bh=0, i, :] (self-contained qwe/qbe) ----------
__global__ void __launch_bounds__(256) means_kernel(const float* __restrict__ edges,
                                                    const float* __restrict__ We,
                                                    const float* __restrict__ be)
{
    const int i = blockIdx.x;
    const int j = threadIdx.x;
    __shared__ float qsm[Dd];
    __shared__ float WesM[EDIM*Dd];
    __shared__ float besM[Dd];
    __shared__ float qwes[EDIM];
    __shared__ float qbes_s;
    __shared__ float red[8];
    if (j < Dd)  qsm[j] = g_q[i*Dd + j];              // bh = 0
    #pragma unroll
    for (int r = 0; r < 4; r++) {
        int idx = j + r*256;
        WesM[idx] = We[(idx >> 6)*INNER + (idx & 63)];  // h = 0
    }
    if (j < Dd) besM[j] = be[j];
    __syncthreads();
    if (j < EDIM) {
        float s = 0.f;
        #pragma unroll
        for (int d = 0; d < Dd; d++) s += qsm[d] * WesM[j*Dd + d];
        qwes[j] = s;
    } else if (j == EDIM) {
        float s = 0.f;
        #pragma unroll
        for (int d = 0; d < Dd; d++) s += qsm[d] * besM[d];
        qbes_s = s;
    }
    __syncthreads();
    float acc = 0.f;
    #pragma unroll
    for (int d = 0; d < Dd; d++) acc += qsm[d] * g_kT[d*Nn + j];   // bh = 0
    const float4* ep = reinterpret_cast<const float4*>(edges) + (i*Nn + j)*4;  // b = 0
    float et = 0.f;
    #pragma unroll
    for (int w = 0; w < 4; w++) {
        float4 e = ep[w];
        et += e.x*qwes[w*4+0] + e.y*qwes[w*4+1] + e.z*qwes[w*4+2] + e.w*qwes[w*4+3];
    }
    float sim = (acc + et + qbes_s) * 0.125f;
    #pragma unroll
    for (int o = 16; o > 0; o >>= 1) sim += __shfl_down_sync(0xffffffffu, sim, o);
    if ((j & 31) == 0) red[j >> 5] = sim;
    __syncthreads();
    if (j == 0) {
        float s = 0.f;
        #pragma unroll
        for (int w = 0; w < 8; w++) s += red[w];
        g_means[i] = s * (1.0f / Nn);
    }
}

// ---------------- fused attention v4: CH=16, fused qwe/qbe ----------------
struct AttnSm {
    float  xs[Nn*XSTR];         // 20KB x for 16 rows: [j][quad p<4 as float4, padded]
    float4 red_out[8*Dd*4];     // 32KB [g][d][p]
    float4 red_ae[CH*8*4];      // 8KB  [u][g2][c4]
    float  ks[Dd*Nn];           // 64KB [d][j]
    float  vs[Nn*Dd];           // 64KB [j][d]
    float  qst[Dd*TI];          // 8KB  [d][ii]
    float  qwe[TI*EDIM];        // 2KB  [ii][c]
    float  Wes[EDIM*Dd];        // 4KB  [c][d]
    float  aes[CH*EDIM];        // 1KB
    float  qbe[TI];
    float  mns[TI];
    float  bes[Dd];
    float  den[CH];
};

__global__ void __launch_bounds__(ATH, 1) attn_kernel(
    const float* __restrict__ edges, const float* __restrict__ adjacency,
    const float* __restrict__ We, const float* __restrict__ be,
    float* __restrict__ out)
{
    extern __shared__ char smraw[];
    AttnSm& sm = *reinterpret_cast<AttnSm*>(smraw);
    const int t  = threadIdx.x;
    const int bh = blockIdx.y;
    const int b  = bh >> 3, h = bh & 7;
    const int i0 = blockIdx.x * TI;

    // ---- tile loads
    {
        const float4* src = reinterpret_cast<const float4*>(&g_kT[bh*Dd*Nn]);
        float4* dst = reinterpret_cast<float4*>(sm.ks);
        #pragma unroll
        for (int r = 0; r < 8; r++) dst[t + r*ATH] = src[t + r*ATH];
        src = reinterpret_cast<const float4*>(&g_v[bh*Nn*Dd]);
        dst = reinterpret_cast<float4*>(sm.vs);
        #pragma unroll
        for (int r = 0; r < 8; r++) dst[t + r*ATH] = src[t + r*ATH];
    }
    #pragma unroll
    for (int r = 0; r < 4; r++) {
        int idx = t + r*ATH;              // 2048 = Dd*TI
        int d = idx >> 5, ii = idx & 31;
        sm.qst[d*TI + ii] = g_q[(bh*Nn + i0 + ii)*Dd + d];
    }
    for (int idx = t; idx < EDIM*Dd; idx += ATH) {
        int c = idx >> 6, d = idx & 63;
        sm.Wes[c*Dd + d] = We[c*INNER + h*Dd + d];
    }
    if (t < TI) sm.mns[t] = g_means[i0 + t];
    if (t < Dd) sm.bes[t] = be[h*Dd + t];
    __syncthreads();

    // ---- fused qwe / qbe from resident tiles
    {
        const int c = t >> 5, il = t & 31;   // warp = fixed c, lanes = ii
        float s = 0.f;
        #pragma unroll
        for (int d = 0; d < Dd; d++) s += sm.qst[d*TI + il] * sm.Wes[c*Dd + d];
        sm.qwe[il*EDIM + c] = s;
        if (t < TI) {
            float qb = 0.f;
            #pragma unroll
            for (int d = 0; d < Dd; d++) qb += sm.qst[d*TI + t] * sm.bes[d];
            sm.qbe[t] = qb;
        }
    }
    __syncthreads();

    const float4* qst4 = reinterpret_cast<const float4*>(sm.qst);  // [d][8 quads]
    const float4* qwe4 = reinterpret_cast<const float4*>(sm.qwe);
    const float*  xsf  = sm.xs;                                    // [j*XSTR + u]

    for (int chnk = 0; chnk < TI/CH; chnk++) {
        const int iib = chnk * CH;
        // ================= phase A: score 8 rows/thread =================
        {
            const int j = t & 255, half = t >> 8;
            const int qb0 = chnk*4 + half*2;     // first quad index
            float4 accA = make_float4(0.f,0.f,0.f,0.f);
            float4 accB = make_float4(0.f,0.f,0.f,0.f);
            #pragma unroll
            for (int d = 0; d < Dd; d++) {
                float kv = sm.ks[d*Nn + j];
                float4 qA = qst4[d*8 + qb0];
                float4 qB = qst4[d*8 + qb0 + 1];
                accA.x += qA.x*kv; accA.y += qA.y*kv; accA.z += qA.z*kv; accA.w += qA.w*kv;
                accB.x += qB.x*kv; accB.y += qB.y*kv; accB.z += qB.z*kv; accB.w += qB.w*kv;
            }
            float xv[8];
            #pragma unroll
            for (int s = 0; s < 8; s++) {
                const int u  = half*8 + s;
                const int ii = iib + u;
                const int i  = i0 + ii;
                const float4* ep = reinterpret_cast<const float4*>(edges) + ((b*Nn + i)*Nn + j)*4;
                float4 e0 = ep[0], e1 = ep[1], e2 = ep[2], e3 = ep[3];
                float adjv = adjacency[(b*Nn + i)*Nn + j];
                float4 q0 = qwe4[ii*4+0], q1 = qwe4[ii*4+1];
                float4 q2 = qwe4[ii*4+2], q3 = qwe4[ii*4+3];
                float et = e0.x*q0.x + e0.y*q0.y + e0.z*q0.z + e0.w*q0.w
                         + e1.x*q1.x + e1.y*q1.y + e1.z*q1.z + e1.w*q1.w
                         + e2.x*q2.x + e2.y*q2.y + e2.z*q2.z + e2.w*q2.w
                         + e3.x*q3.x + e3.y*q3.y + e3.z*q3.z + e3.w*q3.w;
                float a;
                if (s < 4) a = (s==0) ? accA.x : ((s==1) ? accA.y : ((s==2) ? accA.z : accA.w));
                else       a = (s==4) ? accB.x : ((s==5) ? accB.y : ((s==6) ? accB.z : accB.w));
                float sim = (a + et + sm.qbe[ii]) * 0.125f;
                xv[s] = __expf(sim - sm.mns[ii]) * adjv;
            }
            float4* xrow = reinterpret_cast<float4*>(&sm.xs[j*XSTR]);
            xrow[half*2 + 0] = make_float4(xv[0], xv[1], xv[2], xv[3]);
            xrow[half*2 + 1] = make_float4(xv[4], xv[5], xv[6], xv[7]);
        }
        __syncthreads();
        // ================= phase B1: x @ v partials (all 512) =================
        {
            const int d = t & 63, g = t >> 6;
            float4 a0 = make_float4(0.f,0.f,0.f,0.f);
            float4 a1 = make_float4(0.f,0.f,0.f,0.f);
            float4 a2 = make_float4(0.f,0.f,0.f,0.f);
            float4 a3 = make_float4(0.f,0.f,0.f,0.f);
            #pragma unroll 4
            for (int jj = g; jj < Nn; jj += 8) {
                float vv = sm.vs[jj*Dd + d];
                const float4* xrow = reinterpret_cast<const float4*>(&sm.xs[jj*XSTR]);
                float4 xA = xrow[0], xB = xrow[1], xC = xrow[2], xD = xrow[3];
                a0.x += xA.x*vv; a0.y += xA.y*vv; a0.z += xA.z*vv; a0.w += xA.w*vv;
                a1.x += xB.x*vv; a1.y += xB.y*vv; a1.z += xB.z*vv; a1.w += xB.w*vv;
                a2.x += xC.x*vv; a2.y += xC.y*vv; a2.z += xC.z*vv; a2.w += xC.w*vv;
                a3.x += xD.x*vv; a3.y += xD.y*vv; a3.z += xD.z*vv; a3.w += xD.w*vv;
            }
            sm.red_out[(g*Dd + d)*4 + 0] = a0;
            sm.red_out[(g*Dd + d)*4 + 1] = a1;
            sm.red_out[(g*Dd + d)*4 + 2] = a2;
            sm.red_out[(g*Dd + d)*4 + 3] = a3;
        }
        // ================= phase B2: x . edges (GMEM re-read, L2-hot) ========
        {
            const int c4 = t & 3, g2 = (t >> 2) & 7, u = t >> 5;
            const int i = i0 + iib + u;
            const float4* ebase = reinterpret_cast<const float4*>(edges) + (b*Nn + i)*Nn*4;
            float4 ae = make_float4(0.f,0.f,0.f,0.f);
            #pragma unroll 8
            for (int r = 0; r < 32; r++) {
                int jj = g2 + r*8;
                float x = xsf[jj*XSTR + u];
                float4 e = ebase[jj*4 + c4];
                ae.x += x*e.x; ae.y += x*e.y; ae.z += x*e.z; ae.w += x*e.w;
            }
            sm.red_ae[(u*8 + g2)*4 + c4] = ae;
        }
        __syncthreads();
        // ---- reduce aE (threads 0..255) + denominators (threads 256..511)
        if (t < CH*EDIM) {
            const int u = t >> 4, c = t & 15;
            const int c4 = c >> 2, comp = c & 3;
            float s = 0.f;
            #pragma unroll
            for (int g2 = 0; g2 < 8; g2++) {
                float4 p = sm.red_ae[(u*8 + g2)*4 + c4];
                s += (comp==0) ? p.x : ((comp==1) ? p.y : ((comp==2) ? p.z : p.w));
            }
            sm.aes[u*EDIM + c] = s;
        } else {
            const int lane = t & 31, w = (t >> 5) - 8;   // w = 0..7
            #pragma unroll
            for (int q = 0; q < 2; q++) {
                const int u = w*2 + q;
                float s = 0.f;
                #pragma unroll
                for (int r = 0; r < 8; r++) {
                    int jj = lane + r*32;
                    s += xsf[jj*XSTR + u];
                }
                #pragma unroll
                for (int o = 16; o > 0; o >>= 1) s += __shfl_down_sync(0xffffffffu, s, o);
                if (lane == 0) sm.den[u] = s;
            }
        }
        __syncthreads();
        // ================= finalize 16 output rows (all 512, 2 each) ==========
        {
            const int d = t & 63, uh = t >> 6;
            #pragma unroll
            for (int p2 = 0; p2 < 2; p2++) {
                const int u = uh + 8*p2;
                const int p = u >> 2, comp = u & 3;
                float rs = 0.f;
                #pragma unroll
                for (int g = 0; g < 8; g++) {
                    float4 r = sm.red_out[(g*Dd + d)*4 + p];
                    rs += (comp==0) ? r.x : ((comp==1) ? r.y : ((comp==2) ? r.z : r.w));
                }
                float eterm = 0.f;
                #pragma unroll
                for (int c = 0; c < EDIM; c++) eterm += sm.aes[u*EDIM + c] * sm.Wes[c*Dd + d];
                float dn = sm.den[u];
                float scale = (dn != 0.f) ? (1.f / dn) : 0.f;
                float bterm = (dn != 0.f) ? sm.bes[d] : 0.f;
                const int i = i0 + iib + u;
                out[(b*Nn + i)*INNER + h*Dd + d] = (rs + eterm) * scale + bterm;
            }
        }
        __syncthreads();
    }
}

// ---------------- launch ----------------
extern "C" void kernel_launch(void* const* d_in, const int* in_sizes, int n_in,
                              void* d_out, int out_size)
{
    const float* nodes = (const float*)d_in[0];
    const float* edges = (const float*)d_in[1];
    const float* adj   = (const float*)d_in[2];
    const float* Wq = (const float*)d_in[3]; const float* bq = (const float*)d_in[4];
    const float* Wk = (const float*)d_in[5]; const float* bk = (const float*)d_in[6];
    const float* Wv = (const float*)d_in[7]; const float* bv = (const float*)d_in[8];
    const float* We = (const float*)d_in[9]; const float* be = (const float*)d_in[10];
    float* out = (float*)d_out;

    cudaFuncSetAttribute(attn_kernel, cudaFuncAttributeMaxDynamicSharedMemorySize,
                         (int)sizeof(AttnSm));

    proj_kernel<<<dim3(8, 8, 3), 256>>>(nodes, Wq, bq, Wk, bk, Wv, bv);
    means_kernel<<<Nn, 256>>>(edges, We, be);
    attn_kernel<<<dim3(Nn/TI, BHn), ATH, sizeof(AttnSm)>>>(edges, adj, We, be, out);
}

// round 5
// speedup vs baseline: 1.4382x; 1.0562x over previous
#include <cuda_runtime.h>
#include <math.h>

#define Bn 2
#define Nn 256
#define INDIM 256
#define EDIM 16
#define Hh 8
#define Dd 64
#define INNER 512
#define BHn 16
#define TI 32
#define CH 16
#define ATH 512
#define XSTR 20   // float stride per j-row of xs (bank-conflict-free padding)

// ---------------- scratch (device globals; no allocation allowed) ----------------
__device__ float g_q[BHn*Nn*Dd];      // [bh][i][d]
__device__ float g_kT[BHn*Dd*Nn];     // [bh][d][j]
__device__ float g_v[BHn*Nn*Dd];      // [bh][j][d]
__device__ float g_means[Nn];         // row means of sim for bh==0 (reference quirk)

// ---------------- projection GEMM v3: 32x64 tiles, 384 blocks of 128 -------------
__global__ void __launch_bounds__(128) proj_kernel(
    const float* __restrict__ nodes,
    const float* __restrict__ Wq, const float* __restrict__ bq,
    const float* __restrict__ Wk, const float* __restrict__ bk,
    const float* __restrict__ Wv, const float* __restrict__ bv)
{
    const int which = blockIdx.z;
    const float* W    = (which==0) ? Wq : ((which==1) ? Wk : Wv);
    const float* bias = (which==0) ? bq : ((which==1) ? bk : bv);
    __shared__ float As[32][36];   // [k][m], stride 36 keeps float4 alignment
    __shared__ float Bs[32][64];   // [k][n]
    __shared__ float TT[32][69];   // transpose staging for g_kT (scalar access)
    const int row0 = blockIdx.y * 32;
    const int col0 = blockIdx.x * 64;
    const int t = threadIdx.x;
    const int tx = t & 15, ty = t >> 4;   // tx: col quad (0..15), ty: row quad (0..7)
    float acc[4][4];
    #pragma unroll
    for (int u = 0; u < 4; u++)
        #pragma unroll
        for (int w = 0; w < 4; w++) acc[u][w] = 0.f;

    for (int k0 = 0; k0 < INDIM; k0 += 32) {
        #pragma unroll
        for (int r = 0; r < 2; r++) {
            int idx = t + r*128;               // 256 float4 of A
            int row = idx >> 3, kq = idx & 7;
            float4 nv = *reinterpret_cast<const float4*>(&nodes[(row0+row)*INDIM + k0 + kq*4]);
            As[kq*4+0][row] = nv.x; As[kq*4+1][row] = nv.y;
            As[kq*4+2][row] = nv.z; As[kq*4+3][row] = nv.w;
        }
        #pragma unroll
        for (int r = 0; r < 4; r++) {
            int idx = t + r*128;               // 512 float4 of B
            int kk = idx >> 4, c4 = idx & 15;
            *reinterpret_cast<float4*>(&Bs[kk][c4*4]) =
                *reinterpret_cast<const float4*>(&W[(k0+kk)*INNER + col0 + c4*4]);
        }
        __syncthreads();
        #pragma unroll
        for (int k = 0; k < 32; k++) {
            float4 a4 = *reinterpret_cast<const float4*>(&As[k][ty*4]);
            float4 b4 = *reinterpret_cast<const float4*>(&Bs[k][tx*4]);
            acc[0][0] += a4.x*b4.x; acc[0][1] += a4.x*b4.y; acc[0][2] += a4.x*b4.z; acc[0][3] += a4.x*b4.w;
            acc[1][0] += a4.y*b4.x; acc[1][1] += a4.y*b4.y; acc[1][2] += a4.y*b4.z; acc[1][3] += a4.y*b4.w;
            acc[2][0] += a4.z*b4.x; acc[2][1] += a4.z*b4.y; acc[2][2] += a4.z*b4.z; acc[2][3] += a4.z*b4.w;
            acc[3][0] += a4.w*b4.x; acc[3][1] += a4.w*b4.y; acc[3][2] += a4.w*b4.z; acc[3][3] += a4.w*b4.w;
        }
        __syncthreads();
    }

    const int b = row0 >> 8;
    const int i0l = row0 & 255;
    const int h = col0 >> 6;
    const int bh = b*Hh + h;
    float4 bias4 = *reinterpret_cast<const float4*>(&bias[col0 + tx*4]);

    if (which != 1) {
        // coalesced float4 stores, row-major [i][d]
        float* dst = (which == 0) ? g_q : g_v;
        #pragma unroll
        for (int u = 0; u < 4; u++) {
            int i = i0l + ty*4 + u;
            float4 val = make_float4(acc[u][0]+bias4.x, acc[u][1]+bias4.y,
                                     acc[u][2]+bias4.z, acc[u][3]+bias4.w);
            *reinterpret_cast<float4*>(&dst[(bh*Nn + i)*Dd + tx*4]) = val;
        }
    } else {
        // stage to smem, then write g_kT [d][i] coalesced
        #pragma unroll
        for (int u = 0; u < 4; u++) {
            int il = ty*4 + u;
            TT[il][tx*4+0] = acc[u][0]+bias4.x;
            TT[il][tx*4+1] = acc[u][1]+bias4.y;
            TT[il][tx*4+2] = acc[u][2]+bias4.z;
            TT[il][tx*4+3] = acc[u][3]+bias4.w;
        }
        __syncthreads();
        #pragma unroll
        for (int w = 0; w < 16; w++) {
            int idx = t + w*128;               // 2048 = 64 d x 32 i
            int d = idx >> 5, il = idx & 31;
            g_kT[(bh*Dd + d)*Nn + i0l + il] = TT[il][d];
        }
    }
}

// ---------------- row means of sim[bh=0, i, :] (self-contained qwe/qbe) ----------
__global__ void __launch_bounds__(256) means_kernel(const float* __restrict__ edges,
                                                    const float* __restrict__ We,
                                                    const float* __restrict__ be)
{
    const int i = blockIdx.x;
    const int j = threadIdx.x;
    __shared__ float qsm[Dd];
    __shared__ float WesM[EDIM*Dd];
    __shared__ float besM[Dd];
    __shared__ float qwes[EDIM];
    __shared__ float qbes_s;
    __shared__ float red[8];
    if (j < Dd)  qsm[j] = g_q[i*Dd + j];              // bh = 0
    #pragma unroll
    for (int r = 0; r < 4; r++) {
        int idx = j + r*256;
        WesM[idx] = We[(idx >> 6)*INNER + (idx & 63)];  // h = 0
    }
    if (j < Dd) besM[j] = be[j];
    __syncthreads();
    if (j < EDIM) {
        float s = 0.f;
        #pragma unroll
        for (int d = 0; d < Dd; d++) s += qsm[d] * WesM[j*Dd + d];
        qwes[j] = s;
    } else if (j == EDIM) {
        float s = 0.f;
        #pragma unroll
        for (int d = 0; d < Dd; d++) s += qsm[d] * besM[d];
        qbes_s = s;
    }
    __syncthreads();
    float acc = 0.f;
    #pragma unroll
    for (int d = 0; d < Dd; d++) acc += qsm[d] * g_kT[d*Nn + j];   // bh = 0
    const float4* ep = reinterpret_cast<const float4*>(edges) + (i*Nn + j)*4;  // b = 0
    float et = 0.f;
    #pragma unroll
    for (int w = 0; w < 4; w++) {
        float4 e = ep[w];
        et += e.x*qwes[w*4+0] + e.y*qwes[w*4+1] + e.z*qwes[w*4+2] + e.w*qwes[w*4+3];
    }
    float sim = (acc + et + qbes_s) * 0.125f;
    #pragma unroll
    for (int o = 16; o > 0; o >>= 1) sim += __shfl_down_sync(0xffffffffu, sim, o);
    if ((j & 31) == 0) red[j >> 5] = sim;
    __syncthreads();
    if (j == 0) {
        float s = 0.f;
        #pragma unroll
        for (int w = 0; w < 8; w++) s += red[w];
        g_means[i] = s * (1.0f / Nn);
    }
}

// ---------------- fused attention v5: CH=16, pipelined edge loads ----------------
struct AttnSm {
    float  xs[Nn*XSTR];         // 20KB x for 16 rows
    float4 red_out[8*Dd*4];     // 32KB [g][d][p]
    float4 red_ae[CH*8*4];      // 8KB  [u][g2][c4]
    float  ks[Dd*Nn];           // 64KB [d][j]
    float  vs[Nn*Dd];           // 64KB [j][d]
    float  qst[Dd*TI];          // 8KB  [d][ii]
    float  qwe[TI*EDIM];        // 2KB  [ii][c]
    float  Wes[EDIM*Dd];        // 4KB  [c][d]
    float  aes[CH*EDIM];        // 1KB
    float  qbe[TI];
    float  mns[TI];
    float  bes[Dd];
    float  den[CH];
};

__global__ void __launch_bounds__(ATH, 1) attn_kernel(
    const float* __restrict__ edges, const float* __restrict__ adjacency,
    const float* __restrict__ We, const float* __restrict__ be,
    float* __restrict__ out)
{
    extern __shared__ char smraw[];
    AttnSm& sm = *reinterpret_cast<AttnSm*>(smraw);
    const int t  = threadIdx.x;
    const int bh = blockIdx.y;
    const int b  = bh >> 3, h = bh & 7;
    const int i0 = blockIdx.x * TI;

    // ---- tile loads
    {
        const float4* src = reinterpret_cast<const float4*>(&g_kT[bh*Dd*Nn]);
        float4* dst = reinterpret_cast<float4*>(sm.ks);
        #pragma unroll
        for (int r = 0; r < 8; r++) dst[t + r*ATH] = src[t + r*ATH];
        src = reinterpret_cast<const float4*>(&g_v[bh*Nn*Dd]);
        dst = reinterpret_cast<float4*>(sm.vs);
        #pragma unroll
        for (int r = 0; r < 8; r++) dst[t + r*ATH] = src[t + r*ATH];
    }
    #pragma unroll
    for (int r = 0; r < 4; r++) {
        int idx = t + r*ATH;              // 2048 = Dd*TI
        int d = idx >> 5, ii = idx & 31;
        sm.qst[d*TI + ii] = g_q[(bh*Nn + i0 + ii)*Dd + d];
    }
    for (int idx = t; idx < EDIM*Dd; idx += ATH) {
        int c = idx >> 6, d = idx & 63;
        sm.Wes[c*Dd + d] = We[c*INNER + h*Dd + d];
    }
    if (t < TI) sm.mns[t] = g_means[i0 + t];
    if (t < Dd) sm.bes[t] = be[h*Dd + t];
    __syncthreads();

    // ---- fused qwe / qbe from resident tiles
    {
        const int c = t >> 5, il = t & 31;   // warp = fixed c, lanes = ii
        float s = 0.f;
        #pragma unroll
        for (int d = 0; d < Dd; d++) s += sm.qst[d*TI + il] * sm.Wes[c*Dd + d];
        sm.qwe[il*EDIM + c] = s;
        if (t < TI) {
            float qb = 0.f;
            #pragma unroll
            for (int d = 0; d < Dd; d++) qb += sm.qst[d*TI + t] * sm.bes[d];
            sm.qbe[t] = qb;
        }
    }
    __syncthreads();

    const float4* qst4 = reinterpret_cast<const float4*>(sm.qst);  // [d][8 quads]
    const float4* qwe4 = reinterpret_cast<const float4*>(sm.qwe);
    const float*  xsf  = sm.xs;                                    // [j*XSTR + u]
    const float4* edges4 = reinterpret_cast<const float4*>(edges);

    for (int chnk = 0; chnk < TI/CH; chnk++) {
        const int iib = chnk * CH;
        // ================= phase A: score 8 rows/thread, pipelined edges ==========
        {
            const int j = t & 255, half = t >> 8;
            const int qb0 = chnk*4 + half*2;     // first quad index
            const int eBase = ((b*Nn + i0 + iib + half*8)*Nn + j);

            // prefetch row 0 (covers DRAM latency under the d-loop)
            const float4* ep0 = edges4 + (long)eBase*4;
            float4 e0 = ep0[0], e1 = ep0[1], e2 = ep0[2], e3 = ep0[3];
            float adjv = adjacency[eBase];

            float4 accA = make_float4(0.f,0.f,0.f,0.f);
            float4 accB = make_float4(0.f,0.f,0.f,0.f);
            #pragma unroll
            for (int d = 0; d < Dd; d++) {
                float kv = sm.ks[d*Nn + j];
                float4 qA = qst4[d*8 + qb0];
                float4 qB = qst4[d*8 + qb0 + 1];
                accA.x += qA.x*kv; accA.y += qA.y*kv; accA.z += qA.z*kv; accA.w += qA.w*kv;
                accB.x += qB.x*kv; accB.y += qB.y*kv; accB.z += qB.z*kv; accB.w += qB.w*kv;
            }
            float xv[8];
            #pragma unroll
            for (int s = 0; s < 8; s++) {
                float4 n0, n1, n2, n3; float adjn;
                if (s < 7) {   // prefetch next row before consuming current
                    const float4* np = edges4 + (long)(eBase + (s+1)*Nn)*4;
                    n0 = np[0]; n1 = np[1]; n2 = np[2]; n3 = np[3];
                    adjn = adjacency[eBase + (s+1)*Nn];
                } else {
                    n0 = n1 = n2 = n3 = make_float4(0.f,0.f,0.f,0.f);
                    adjn = 0.f;
                }
                const int u  = half*8 + s;
                const int ii = iib + u;
                float4 q0 = qwe4[ii*4+0], q1 = qwe4[ii*4+1];
                float4 q2 = qwe4[ii*4+2], q3 = qwe4[ii*4+3];
                float et = e0.x*q0.x + e0.y*q0.y + e0.z*q0.z + e0.w*q0.w
                         + e1.x*q1.x + e1.y*q1.y + e1.z*q1.z + e1.w*q1.w
                         + e2.x*q2.x + e2.y*q2.y + e2.z*q2.z + e2.w*q2.w
                         + e3.x*q3.x + e3.y*q3.y + e3.z*q3.z + e3.w*q3.w;
                float a;
                if (s < 4) a = (s==0) ? accA.x : ((s==1) ? accA.y : ((s==2) ? accA.z : accA.w));
                else       a = (s==4) ? accB.x : ((s==5) ? accB.y : ((s==6) ? accB.z : accB.w));
                float sim = (a + et + sm.qbe[ii]) * 0.125f;
                xv[s] = __expf(sim - sm.mns[ii]) * adjv;
                e0 = n0; e1 = n1; e2 = n2; e3 = n3; adjv = adjn;
            }
            float4* xrow = reinterpret_cast<float4*>(&sm.xs[j*XSTR]);
            xrow[half*2 + 0] = make_float4(xv[0], xv[1], xv[2], xv[3]);
            xrow[half*2 + 1] = make_float4(xv[4], xv[5], xv[6], xv[7]);
        }
        __syncthreads();
        // ================= phase B1: x @ v partials (all 512) =================
        {
            const int d = t & 63, g = t >> 6;
            float4 a0 = make_float4(0.f,0.f,0.f,0.f);
            float4 a1 = make_float4(0.f,0.f,0.f,0.f);
            float4 a2 = make_float4(0.f,0.f,0.f,0.f);
            float4 a3 = make_float4(0.f,0.f,0.f,0.f);
            #pragma unroll 4
            for (int jj = g; jj < Nn; jj += 8) {
                float vv = sm.vs[jj*Dd + d];
                const float4* xrow = reinterpret_cast<const float4*>(&sm.xs[jj*XSTR]);
                float4 xA = xrow[0], xB = xrow[1], xC = xrow[2], xD = xrow[3];
                a0.x += xA.x*vv; a0.y += xA.y*vv; a0.z += xA.z*vv; a0.w += xA.w*vv;
                a1.x += xB.x*vv; a1.y += xB.y*vv; a1.z += xB.z*vv; a1.w += xB.w*vv;
                a2.x += xC.x*vv; a2.y += xC.y*vv; a2.z += xC.z*vv; a2.w += xC.w*vv;
                a3.x += xD.x*vv; a3.y += xD.y*vv; a3.z += xD.z*vv; a3.w += xD.w*vv;
            }
            sm.red_out[(g*Dd + d)*4 + 0] = a0;
            sm.red_out[(g*Dd + d)*4 + 1] = a1;
            sm.red_out[(g*Dd + d)*4 + 2] = a2;
            sm.red_out[(g*Dd + d)*4 + 3] = a3;
        }
        // ================= phase B2: x . edges (GMEM re-read, L2-hot) ========
        {
            const int c4 = t & 3, g2 = (t >> 2) & 7, u = t >> 5;
            const int i = i0 + iib + u;
            const float4* ebase = edges4 + (long)(b*Nn + i)*Nn*4;
            float4 ae = make_float4(0.f,0.f,0.f,0.f);
            #pragma unroll 8
            for (int r = 0; r < 32; r++) {
                int jj = g2 + r*8;
                float x = xsf[jj*XSTR + u];
                float4 e = ebase[jj*4 + c4];
                ae.x += x*e.x; ae.y += x*e.y; ae.z += x*e.z; ae.w += x*e.w;
            }
            sm.red_ae[(u*8 + g2)*4 + c4] = ae;
        }
        __syncthreads();
        // ---- reduce aE (threads 0..255) + denominators (threads 256..511)
        if (t < CH*EDIM) {
            const int u = t >> 4, c = t & 15;
            const int c4 = c >> 2, comp = c & 3;
            float s = 0.f;
            #pragma unroll
            for (int g2 = 0; g2 < 8; g2++) {
                float4 p = sm.red_ae[(u*8 + g2)*4 + c4];
                s += (comp==0) ? p.x : ((comp==1) ? p.y : ((comp==2) ? p.z : p.w));
            }
            sm.aes[u*EDIM + c] = s;
        } else {
            const int lane = t & 31, w = (t >> 5) - 8;   // w = 0..7
            #pragma unroll
            for (int q = 0; q < 2; q++) {
                const int u = w*2 + q;
                float s = 0.f;
                #pragma unroll
                for (int r = 0; r < 8; r++) {
                    int jj = lane + r*32;
                    s += xsf[jj*XSTR + u];
                }
                #pragma unroll
                for (int o = 16; o > 0; o >>= 1) s += __shfl_down_sync(0xffffffffu, s, o);
                if (lane == 0) sm.den[u] = s;
            }
        }
        __syncthreads();
        // ================= finalize 16 output rows (all 512, 2 each) ==========
        {
            const int d = t & 63, uh = t >> 6;
            #pragma unroll
            for (int p2 = 0; p2 < 2; p2++) {
                const int u = uh + 8*p2;
                const int p = u >> 2, comp = u & 3;
                float rs = 0.f;
                #pragma unroll
                for (int g = 0; g < 8; g++) {
                    float4 r = sm.red_out[(g*Dd + d)*4 + p];
                    rs += (comp==0) ? r.x : ((comp==1) ? r.y : ((comp==2) ? r.z : r.w));
                }
                float eterm = 0.f;
                #pragma unroll
                for (int c = 0; c < EDIM; c++) eterm += sm.aes[u*EDIM + c] * sm.Wes[c*Dd + d];
                float dn = sm.den[u];
                float scale = (dn != 0.f) ? (1.f / dn) : 0.f;
                float bterm = (dn != 0.f) ? sm.bes[d] : 0.f;
                const int i = i0 + iib + u;
                out[(b*Nn + i)*INNER + h*Dd + d] = (rs + eterm) * scale + bterm;
            }
        }
        __syncthreads();
    }
}

// ---------------- launch ----------------
extern "C" void kernel_launch(void* const* d_in, const int* in_sizes, int n_in,
                              void* d_out, int out_size)
{
    const float* nodes = (const float*)d_in[0];
    const float* edges = (const float*)d_in[1];
    const float* adj   = (const float*)d_in[2];
    const float* Wq = (const float*)d_in[3]; const float* bq = (const float*)d_in[4];
    const float* Wk = (const float*)d_in[5]; const float* bk = (const float*)d_in[6];
    const float* Wv = (const float*)d_in[7]; const float* bv = (const float*)d_in[8];
    const float* We = (const float*)d_in[9]; const float* be = (const float*)d_in[10];
    float* out = (float*)d_out;

    cudaFuncSetAttribute(attn_kernel, cudaFuncAttributeMaxDynamicSharedMemorySize,
                         (int)sizeof(AttnSm));

    proj_kernel<<<dim3(8, 16, 3), 128>>>(nodes, Wq, bq, Wk, bk, Wv, bv);
    means_kernel<<<Nn, 256>>>(edges, We, be);
    attn_kernel<<<dim3(Nn/TI, BHn), ATH, sizeof(AttnSm)>>>(edges, adj, We, be, out);
}